// round 8
// baseline (speedup 1.0000x reference)
#include <cuda_runtime.h>
#include <cuda_bf16.h>
#include <cstdint>

#define NROWS 65536
#define D 64
#define K 1024
#define NSTRIPS 2048         // 32 rows each
#define ST 1294              // strips 0..1293 tensor path, rest exact scalar
#define TAU 2e-4f

// Static scratch (no allocations allowed). Zero-init only needed for g_pool
// on the very first call; vq_fin resets it every call for graph replay.
__device__ int    g_pool;
__device__ __nv_bfloat16 g_emb_bf16[K * D];
__device__ float  g_ee[K];
__device__ double g_part[NSTRIPS];
__device__ double g_part2[NSTRIPS];
__device__ int    g_rcnt[NSTRIPS];
__device__ int    g_rrows[NSTRIPS * 32];

__device__ __forceinline__ uint32_t pack_bf16x2(float a, float b) {
    __nv_bfloat162 h = __floats2bfloat162_rn(a, b);
    return *(uint32_t*)&h;
}
__device__ __forceinline__ void mma16816(float& c0, float& c1, float& c2, float& c3,
                                         uint32_t a0, uint32_t a1, uint32_t a2, uint32_t a3,
                                         uint32_t b0, uint32_t b1) {
    asm volatile("mma.sync.aligned.m16n8k16.row.col.f32.bf16.bf16.f32 "
                 "{%0,%1,%2,%3}, {%4,%5,%6,%7}, {%8,%9}, {%0,%1,%2,%3};"
                 : "+f"(c0), "+f"(c1), "+f"(c2), "+f"(c3)
                 : "r"(a0), "r"(a1), "r"(a2), "r"(a3), "r"(b0), "r"(b1));
}

struct MinState { float m1, m2; int idx; };
__device__ __forceinline__ void upd(MinState& s, float d, int e) {
    float mx = fmaxf(s.m1, d);
    bool  lt = d < s.m1;
    s.m1  = fminf(s.m1, d);
    s.idx = lt ? e : s.idx;
    s.m2  = fminf(s.m2, mx);
}
__device__ __forceinline__ void red4(MinState& s) {
    #pragma unroll
    for (int off = 1; off <= 2; off <<= 1) {
        float om1 = __shfl_xor_sync(0xffffffffu, s.m1, off);
        float om2 = __shfl_xor_sync(0xffffffffu, s.m2, off);
        int   oix = __shfl_xor_sync(0xffffffffu, s.idx, off);
        bool take = (om1 < s.m1) || (om1 == s.m1 && oix < s.idx);
        float nm2 = fminf(fminf(s.m2, om2), fmaxf(s.m1, om1));
        s.m1  = fminf(s.m1, om1);
        s.idx = take ? oix : s.idx;
        s.m2  = nm2;
    }
}

__global__ void vq_pre_kernel(const float* __restrict__ emb) {
    int k = blockIdx.x * blockDim.x + threadIdx.x;
    if (k < K) {
        const float4* e = (const float4*)(emb + k * D);
        float s = 0.f;
        #pragma unroll
        for (int j = 0; j < 16; ++j) {
            float4 v = e[j];
            s += v.x * v.x; s += v.y * v.y; s += v.z * v.z; s += v.w * v.w;
            *(uint32_t*)(g_emb_bf16 + k * D + j * 4)     = pack_bf16x2(v.x, v.y);
            *(uint32_t*)(g_emb_bf16 + k * D + j * 4 + 2) = pack_bf16x2(v.z, v.w);
        }
        g_ee[k] = s;
    }
}

// ---------- tensor strip: bf16 MMA + TAU guard (validated path) ----------
__device__ void tensor_strip(int s, int warp_sm, float* s_m1, float* s_m2, int* s_ix,
                             const float* __restrict__ z,
                             const float* __restrict__ emb,
                             float* __restrict__ out) {
    const int lane = threadIdx.x & 31;
    const int g = lane >> 2, t = lane & 3;
    const int base = s * 32;

    // A fragments from z (register-resident for the strip).
    uint32_t A[2][4][4];
    #pragma unroll
    for (int tl = 0; tl < 2; ++tl) {
        const float* r0 = z + (size_t)(base + tl * 16 + g) * D;
        const float* r1 = r0 + 8 * D;
        #pragma unroll
        for (int ks = 0; ks < 4; ++ks) {
            int kb = ks * 16 + 2 * t;
            float2 u0 = *(const float2*)(r0 + kb);
            float2 u1 = *(const float2*)(r1 + kb);
            float2 u2 = *(const float2*)(r0 + kb + 8);
            float2 u3 = *(const float2*)(r1 + kb + 8);
            A[tl][ks][0] = pack_bf16x2(u0.x, u0.y);
            A[tl][ks][1] = pack_bf16x2(u1.x, u1.y);
            A[tl][ks][2] = pack_bf16x2(u2.x, u2.y);
            A[tl][ks][3] = pack_bf16x2(u3.x, u3.y);
        }
    }

    MinState U0 = {3.4e38f, 3.4e38f, 0}, L0 = U0, U1 = U0, L1 = U0;

    for (int nt = 0; nt < K / 8; ++nt) {
        const int nb = nt * 8;
        // B direct from global bf16 codebook (L1-resident after first strip).
        const __nv_bfloat16* brow = g_emb_bf16 + (size_t)(nb + g) * D + 2 * t;
        float c00 = 0.f, c01 = 0.f, c02 = 0.f, c03 = 0.f;
        float c10 = 0.f, c11 = 0.f, c12 = 0.f, c13 = 0.f;
        #pragma unroll
        for (int ks = 0; ks < 4; ++ks) {
            uint32_t b0 = __ldg((const uint32_t*)(brow + ks * 16));
            uint32_t b1 = __ldg((const uint32_t*)(brow + ks * 16 + 8));
            mma16816(c00, c01, c02, c03,
                     A[0][ks][0], A[0][ks][1], A[0][ks][2], A[0][ks][3], b0, b1);
            mma16816(c10, c11, c12, c13,
                     A[1][ks][0], A[1][ks][1], A[1][ks][2], A[1][ks][3], b0, b1);
        }
        float2 ee = __ldg((const float2*)(g_ee + nb + 2 * t));
        int e0 = nb + 2 * t, e1 = e0 + 1;
        upd(U0, fmaf(-2.f, c00, ee.x), e0);
        upd(U0, fmaf(-2.f, c01, ee.y), e1);
        upd(L0, fmaf(-2.f, c02, ee.x), e0);
        upd(L0, fmaf(-2.f, c03, ee.y), e1);
        upd(U1, fmaf(-2.f, c10, ee.x), e0);
        upd(U1, fmaf(-2.f, c11, ee.y), e1);
        upd(L1, fmaf(-2.f, c12, ee.x), e0);
        upd(L1, fmaf(-2.f, c13, ee.y), e1);
    }

    red4(U0); red4(L0); red4(U1); red4(L1);
    float* m1 = s_m1 + warp_sm * 32;
    float* m2 = s_m2 + warp_sm * 32;
    int*   ix = s_ix + warp_sm * 32;
    if (t == 0) {
        m1[g]      = U0.m1; m2[g]      = U0.m2; ix[g]      = U0.idx;
        m1[g + 8]  = L0.m1; m2[g + 8]  = L0.m2; ix[g + 8]  = L0.idx;
        m1[g + 16] = U1.m1; m2[g + 16] = U1.m2; ix[g + 16] = U1.idx;
        m1[g + 24] = L1.m1; m2[g + 24] = L1.m2; ix[g + 24] = L1.idx;
    }
    __syncwarp();

    // Epilogue: lane = row within strip.
    const int row = base + lane;
    float rm1 = m1[lane], rm2 = m2[lane];
    int   idx1 = ix[lane];
    bool  tie = (rm2 - rm1 < TAU);
    uint32_t mask = __ballot_sync(0xffffffffu, tie);

    double lacc = 0.0;
    if (tie) {
        int pos = __popc(mask & ((1u << lane) - 1u));
        g_rrows[s * 32 + pos] = row;
    } else {
        const float4* zp = (const float4*)z + (size_t)row * 16;
        const float4* eb = (const float4*)emb + (size_t)idx1 * 16;
        float4* op = (float4*)out + (size_t)row * 16;
        #pragma unroll
        for (int j = 0; j < 16; ++j) {
            float4 q = eb[j];
            float4 zv = zp[j];
            op[j] = q;
            float dx = q.x - zv.x, dy = q.y - zv.y;
            float dz = q.z - zv.z, dw = q.w - zv.w;
            lacc += (double)dx * dx + (double)dy * dy
                  + (double)dz * dz + (double)dw * dw;
        }
    }
    #pragma unroll
    for (int off = 16; off; off >>= 1)
        lacc += __shfl_down_sync(0xffffffffu, lacc, off);
    if (lane == 0) {
        g_rcnt[s] = __popc(mask);
        g_part[s] = lacc;
    }
}

// ---------- scalar strip: exact fp32, R1 arithmetic (no rescore needed) ----------
__device__ void scalar_strip(int s,
                             const float* __restrict__ z,
                             const float* __restrict__ emb,
                             float* __restrict__ out) {
    const int lane = threadIdx.x & 31;
    const int row  = s * 32 + lane;

    float4 zr[16];
    const float4* zp = (const float4*)z + (size_t)row * 16;
    #pragma unroll
    for (int j = 0; j < 16; ++j) zr[j] = zp[j];

    float zz = 0.f;
    #pragma unroll
    for (int j = 0; j < 16; ++j) {
        zz += zr[j].x * zr[j].x; zz += zr[j].y * zr[j].y;
        zz += zr[j].z * zr[j].z; zz += zr[j].w * zr[j].w;
    }

    float dmin = 3.4e38f;
    int   best = 0;
    #pragma unroll 2
    for (int e = 0; e < K; ++e) {
        const float4* ev = (const float4*)emb + (size_t)e * 16;
        float ze = 0.f;
        #pragma unroll
        for (int j = 0; j < 16; ++j) {
            float4 v = __ldg(&ev[j]);   // broadcast (uniform) load, L2-resident
            ze += zr[j].x * v.x; ze += zr[j].y * v.y;
            ze += zr[j].z * v.z; ze += zr[j].w * v.w;
        }
        float d = (zz - 2.0f * ze) + __ldg(&g_ee[e]);
        if (d < dmin) { dmin = d; best = e; }   // first-min (jnp.argmin)
    }

    double lacc = 0.0;
    const float4* eb = (const float4*)emb + (size_t)best * 16;
    float4* op = (float4*)out + (size_t)row * 16;
    #pragma unroll
    for (int j = 0; j < 16; ++j) {
        float4 q = eb[j];
        op[j] = q;
        float dx = q.x - zr[j].x, dy = q.y - zr[j].y;
        float dz = q.z - zr[j].z, dw = q.w - zr[j].w;
        lacc += (double)dx * dx + (double)dy * dy
              + (double)dz * dz + (double)dw * dw;
    }
    #pragma unroll
    for (int off = 16; off; off >>= 1)
        lacc += __shfl_down_sync(0xffffffffu, lacc, off);
    if (lane == 0) {
        g_rcnt[s] = 0;
        g_part[s] = lacc;
    }
}

__global__ __launch_bounds__(256, 2)
void vq_main_kernel(const float* __restrict__ z,
                    const float* __restrict__ emb,
                    float* __restrict__ out) {
    __shared__ float s_m1[8 * 32], s_m2[8 * 32];
    __shared__ int   s_ix[8 * 32];
    const int warp_sm = threadIdx.x >> 5;
    const int lane    = threadIdx.x & 31;

    for (;;) {
        int s;
        if (lane == 0) s = atomicAdd(&g_pool, 1);
        s = __shfl_sync(0xffffffffu, s, 0);
        if (s >= NSTRIPS) break;
        if (s < ST) tensor_strip(s, warp_sm, s_m1, s_m2, s_ix, z, emb, out);
        else        scalar_strip(s, z, emb, out);
    }
}

// Exact fp32 rescan for near-tie tensor rows. Block b serves strip b's list.
__global__ __launch_bounds__(256)
void vq_rescore_kernel(const float* __restrict__ z,
                       const float* __restrict__ emb,
                       float* __restrict__ out) {
    __shared__ float s_emb[128 * 69];
    __shared__ float s_zrow[8 * 64];
    __shared__ int   s_rows[8];
    __shared__ double s_red[8];

    const int b = blockIdx.x;
    const int n = g_rcnt[b];
    const int tid = threadIdx.x;
    const int w = tid >> 5, l = tid & 31;

    if (n == 0) { if (tid == 0) g_part2[b] = 0.0; return; }

    double wacc = 0.0;
    for (int base = 0; base < n; base += 8) {
        __syncthreads();
        if (tid < 8)
            s_rows[tid] = (base + tid < n) ? g_rrows[b * 32 + base + tid] : -1;
        __syncthreads();
        if (tid < 8 * 16) {
            int rw = tid >> 4, j = tid & 15;
            int r = s_rows[rw];
            if (r >= 0)
                *(float4*)(s_zrow + rw * 64 + j * 4) = ((const float4*)z)[(size_t)r * 16 + j];
        }
        __syncthreads();

        int myrow = s_rows[w];
        float zz = 0.f;
        if (myrow >= 0)
            for (int i = 0; i < 64; ++i) { float v = s_zrow[w * 64 + i]; zz += v * v; }

        float dmin = 3.4e38f;
        int   bestk = 0;

        for (int tt = 0; tt < K / 128; ++tt) {
            __syncthreads();
            for (int f = tid; f < 128 * 16; f += 256) {
                int e = f >> 4, j = f & 15;
                float4 v = ((const float4*)emb)[(size_t)(tt * 128 + e) * 16 + j];
                float* dst = s_emb + e * 69 + j * 4;
                dst[0] = v.x; dst[1] = v.y; dst[2] = v.z; dst[3] = v.w;
            }
            __syncthreads();
            if (myrow >= 0) {
                #pragma unroll
                for (int q = 0; q < 4; ++q) {
                    int el = q * 32 + l;
                    const float* e = s_emb + el * 69;
                    float ze = 0.f;
                    for (int i = 0; i < 64; ++i) ze += s_zrow[w * 64 + i] * e[i];
                    int ge = tt * 128 + el;
                    float d = (zz - 2.0f * ze) + g_ee[ge];
                    if (d < dmin) { dmin = d; bestk = ge; }
                }
            }
        }

        #pragma unroll
        for (int off = 16; off; off >>= 1) {
            float od = __shfl_down_sync(0xffffffffu, dmin, off);
            int   oi = __shfl_down_sync(0xffffffffu, bestk, off);
            if (od < dmin || (od == dmin && oi < bestk)) { dmin = od; bestk = oi; }
        }

        if (myrow >= 0 && l == 0) {
            const float4* eb = (const float4*)emb + (size_t)bestk * 16;
            float4* op = (float4*)out + (size_t)myrow * 16;
            for (int j = 0; j < 16; ++j) {
                float4 q = eb[j];
                float zx = s_zrow[w * 64 + j * 4 + 0];
                float zy = s_zrow[w * 64 + j * 4 + 1];
                float zzv = s_zrow[w * 64 + j * 4 + 2];
                float zw = s_zrow[w * 64 + j * 4 + 3];
                op[j] = q;
                float dx = q.x - zx, dy = q.y - zy, dz = q.z - zzv, dw = q.w - zw;
                wacc += (double)dx * dx + (double)dy * dy
                      + (double)dz * dz + (double)dw * dw;
            }
        }
    }
    __syncthreads();
    if (l == 0) s_red[w] = wacc;
    __syncthreads();
    if (tid == 0) {
        double s2 = 0.0;
        #pragma unroll
        for (int i = 0; i < 8; ++i) s2 += s_red[i];
        g_part2[b] = s2;
    }
}

__global__ __launch_bounds__(256)
void vq_fin_kernel(float* __restrict__ out, int out_size) {
    __shared__ double s_red[8];
    int tid = threadIdx.x;
    double v = 0.0;
    for (int i = tid; i < NSTRIPS; i += 256)
        v += g_part[i] + g_part2[i];
    #pragma unroll
    for (int off = 16; off; off >>= 1)
        v += __shfl_down_sync(0xffffffffu, v, off);
    if ((tid & 31) == 0) s_red[tid >> 5] = v;
    __syncthreads();
    if (tid == 0) {
        double s = 0.0;
        #pragma unroll
        for (int i = 0; i < 8; ++i) s += s_red[i];
        if (out_size > NROWS * D)
            out[NROWS * D] = (float)(1.25 * s / (double)((long long)NROWS * D));
        g_pool = 0;   // reset work pool for next graph replay
    }
}

extern "C" void kernel_launch(void* const* d_in, const int* in_sizes, int n_in,
                              void* d_out, int out_size) {
    const float* z   = (const float*)d_in[0];
    const float* emb = (const float*)d_in[1];
    if (n_in >= 2 && in_sizes[0] == K * D && in_sizes[1] == NROWS * D) {
        z   = (const float*)d_in[1];
        emb = (const float*)d_in[0];
    }
    float* out = (float*)d_out;

    vq_pre_kernel<<<8, 128>>>(emb);
    vq_main_kernel<<<296, 256>>>(z, emb, out);
    vq_rescore_kernel<<<NSTRIPS, 256>>>(z, emb, out);
    vq_fin_kernel<<<1, 256>>>(out, out_size);
}

// round 9
// speedup vs baseline: 3.2052x; 3.2052x over previous
#include <cuda_runtime.h>
#include <cuda_bf16.h>
#include <cstdint>

#define NROWS 65536
#define D 64
#define K 1024
#define BLOCK 128          // 4 warps; 32 rows/warp; 128 rows/CTA; 512 CTAs
#define NCTAS (NROWS / BLOCK)
#define CH 128             // codebook entries per smem chunk
#define NCH (K / CH)
#define ESTRIDE 144        // padded per-entry smem stride (bytes), conflict-free
#define TAU 2.5e-4f
#define RW 8

// Static scratch (no allocations). g_done starts 0 and is reset each call.
__device__ uint4  g_emb_perm[K * 8];   // t-major permuted bf16 codebook, 128B/entry
__device__ float  g_ee[K];
__device__ double g_part[NCTAS];
__device__ double g_part2[NCTAS];
__device__ int    g_rcnt[NCTAS];
__device__ int    g_rrows[NROWS];
__device__ int    g_done;

__device__ __forceinline__ uint32_t pack_bf16x2(float a, float b) {
    __nv_bfloat162 h = __floats2bfloat162_rn(a, b);
    return *(uint32_t*)&h;
}
__device__ __forceinline__ void mma16816(float& c0, float& c1, float& c2, float& c3,
                                         uint32_t a0, uint32_t a1, uint32_t a2, uint32_t a3,
                                         uint32_t b0, uint32_t b1) {
    asm volatile("mma.sync.aligned.m16n8k16.row.col.f32.bf16.bf16.f32 "
                 "{%0,%1,%2,%3}, {%4,%5,%6,%7}, {%8,%9}, {%0,%1,%2,%3};"
                 : "+f"(c0), "+f"(c1), "+f"(c2), "+f"(c3)
                 : "r"(a0), "r"(a1), "r"(a2), "r"(a3), "r"(b0), "r"(b1));
}

// Pack entry index into low 10 mantissa bits; perturbation <= ~4e-6 on |d|<=0.05.
__device__ __forceinline__ float packd(float d, uint32_t e) {
    return __uint_as_float((__float_as_uint(d) & 0xFFFFFC00u) | e);
}
// Branch-free min1/min2 on packed values (index rides in m1's mantissa).
__device__ __forceinline__ void upd(float& m1, float& m2, float f) {
    float mx = fmaxf(m1, f);
    m1 = fminf(m1, f);
    m2 = fminf(m2, mx);
}
__device__ __forceinline__ void red4(float& m1, float& m2) {
    #pragma unroll
    for (int off = 1; off <= 2; off <<= 1) {
        float om1 = __shfl_xor_sync(0xffffffffu, m1, off);
        float om2 = __shfl_xor_sync(0xffffffffu, m2, off);
        m2 = fminf(fminf(m2, om2), fmaxf(m1, om1));
        m1 = fminf(m1, om1);
    }
}

__global__ void vq_pre_kernel(const float* __restrict__ emb) {
    int k = blockIdx.x * blockDim.x + threadIdx.x;
    if (k < K) {
        const float4* e = (const float4*)(emb + k * D);
        float s = 0.f;
        uint32_t p[32];
        #pragma unroll
        for (int j = 0; j < 16; ++j) {
            float4 v = e[j];
            s += v.x * v.x; s += v.y * v.y; s += v.z * v.z; s += v.w * v.w;
            p[2 * j]     = pack_bf16x2(v.x, v.y);
            p[2 * j + 1] = pack_bf16x2(v.z, v.w);
        }
        g_ee[k] = s;
        // t-major permutation: group t holds k-pairs [t, t+4, ..., t+28].
        uint4* dst = g_emb_perm + (size_t)k * 8;
        #pragma unroll
        for (int t = 0; t < 4; ++t) {
            dst[t * 2]     = make_uint4(p[t], p[t + 4], p[t + 8],  p[t + 12]);
            dst[t * 2 + 1] = make_uint4(p[t + 16], p[t + 20], p[t + 24], p[t + 28]);
        }
    }
}

__global__ __launch_bounds__(BLOCK, 6)
void vq_main_kernel(const float* __restrict__ z,
                    const float* __restrict__ emb,
                    float* __restrict__ out) {
    __shared__ __align__(16) char s_b[CH * ESTRIDE];   // 18 KB codebook chunk
    __shared__ float  s_ee[K];
    __shared__ float  s_m1[BLOCK], s_m2[BLOCK];
    __shared__ int    s_wc[5];
    __shared__ double s_red[BLOCK / 32];

    const int tid   = threadIdx.x;
    const int warp  = tid >> 5;
    const int lane  = tid & 31;
    const int g     = lane >> 2;
    const int t     = lane & 3;
    const int rbase = blockIdx.x * BLOCK;
    const int wrow  = rbase + warp * 32;

    #pragma unroll
    for (int i = 0; i < K / BLOCK; ++i)
        s_ee[i * BLOCK + tid] = g_ee[i * BLOCK + tid];

    // A fragments: z rows bf16, register-resident for whole kernel.
    uint32_t A[2][4][4];
    #pragma unroll
    for (int tl = 0; tl < 2; ++tl) {
        const float* r0 = z + (size_t)(wrow + tl * 16 + g) * D;
        const float* r1 = r0 + 8 * D;
        #pragma unroll
        for (int ks = 0; ks < 4; ++ks) {
            int kb = ks * 16 + 2 * t;
            float2 u0 = *(const float2*)(r0 + kb);
            float2 u1 = *(const float2*)(r1 + kb);
            float2 u2 = *(const float2*)(r0 + kb + 8);
            float2 u3 = *(const float2*)(r1 + kb + 8);
            A[tl][ks][0] = pack_bf16x2(u0.x, u0.y);
            A[tl][ks][1] = pack_bf16x2(u1.x, u1.y);
            A[tl][ks][2] = pack_bf16x2(u2.x, u2.y);
            A[tl][ks][3] = pack_bf16x2(u3.x, u3.y);
        }
    }

    float u0m1 = 3.0e38f, u0m2 = 3.0e38f, l0m1 = 3.0e38f, l0m2 = 3.0e38f;
    float u1m1 = 3.0e38f, u1m2 = 3.0e38f, l1m1 = 3.0e38f, l1m2 = 3.0e38f;

    for (int ch = 0; ch < NCH; ++ch) {
        __syncthreads();
        {   // Stage 128 permuted entries: 1 per thread, 8 x 16B.
            const uint4* src = g_emb_perm + (size_t)(ch * CH + tid) * 8;
            uint4* dst = (uint4*)(s_b + tid * ESTRIDE);
            #pragma unroll
            for (int i = 0; i < 8; ++i) dst[i] = src[i];
        }
        __syncthreads();

        for (int nt = 0; nt < CH / 8; ++nt) {
            const int nbl = nt * 8;
            const int nb  = ch * CH + nbl;
            // All 4 k-steps of both B regs in 2 LDS.128 (t-major layout).
            const char* bp = s_b + (nbl + g) * ESTRIDE + t * 32;
            uint4 q0 = *(const uint4*)bp;
            uint4 q1 = *(const uint4*)(bp + 16);

            float c00 = 0.f, c01 = 0.f, c02 = 0.f, c03 = 0.f;
            float c10 = 0.f, c11 = 0.f, c12 = 0.f, c13 = 0.f;
            mma16816(c00, c01, c02, c03, A[0][0][0], A[0][0][1], A[0][0][2], A[0][0][3], q0.x, q0.y);
            mma16816(c10, c11, c12, c13, A[1][0][0], A[1][0][1], A[1][0][2], A[1][0][3], q0.x, q0.y);
            mma16816(c00, c01, c02, c03, A[0][1][0], A[0][1][1], A[0][1][2], A[0][1][3], q0.z, q0.w);
            mma16816(c10, c11, c12, c13, A[1][1][0], A[1][1][1], A[1][1][2], A[1][1][3], q0.z, q0.w);
            mma16816(c00, c01, c02, c03, A[0][2][0], A[0][2][1], A[0][2][2], A[0][2][3], q1.x, q1.y);
            mma16816(c10, c11, c12, c13, A[1][2][0], A[1][2][1], A[1][2][2], A[1][2][3], q1.x, q1.y);
            mma16816(c00, c01, c02, c03, A[0][3][0], A[0][3][1], A[0][3][2], A[0][3][3], q1.z, q1.w);
            mma16816(c10, c11, c12, c13, A[1][3][0], A[1][3][1], A[1][3][2], A[1][3][3], q1.z, q1.w);

            float2 ee = *(const float2*)(s_ee + nb + 2 * t);
            uint32_t e0 = nb + 2 * t, e1 = e0 + 1;
            upd(u0m1, u0m2, packd(fmaf(-2.f, c00, ee.x), e0));
            upd(u0m1, u0m2, packd(fmaf(-2.f, c01, ee.y), e1));
            upd(l0m1, l0m2, packd(fmaf(-2.f, c02, ee.x), e0));
            upd(l0m1, l0m2, packd(fmaf(-2.f, c03, ee.y), e1));
            upd(u1m1, u1m2, packd(fmaf(-2.f, c10, ee.x), e0));
            upd(u1m1, u1m2, packd(fmaf(-2.f, c11, ee.y), e1));
            upd(l1m1, l1m2, packd(fmaf(-2.f, c12, ee.x), e0));
            upd(l1m1, l1m2, packd(fmaf(-2.f, c13, ee.y), e1));
        }
    }

    red4(u0m1, u0m2); red4(l0m1, l0m2); red4(u1m1, u1m2); red4(l1m1, l1m2);
    if (t == 0) {
        int lr = warp * 32 + g;
        s_m1[lr]      = u0m1; s_m2[lr]      = u0m2;
        s_m1[lr + 8]  = l0m1; s_m2[lr + 8]  = l0m2;
        s_m1[lr + 16] = u1m1; s_m2[lr + 16] = u1m2;
        s_m1[lr + 24] = l1m1; s_m2[lr + 24] = l1m2;
    }
    __syncthreads();

    // Epilogue: one thread per row. Deterministic rescue list (warp-ordered).
    const int row = rbase + tid;
    float m1 = s_m1[tid], m2 = s_m2[tid];
    int   idx1 = (int)(__float_as_uint(m1) & 1023u);
    bool  tie = (m2 - m1 < TAU);
    uint32_t mask = __ballot_sync(0xffffffffu, tie);
    if (lane == 0) s_wc[warp] = __popc(mask);
    __syncthreads();
    int wbase = 0;
    #pragma unroll
    for (int wv = 0; wv < 4; ++wv) wbase += (wv < warp) ? s_wc[wv] : 0;

    double lacc = 0.0;
    const float4* zp = (const float4*)z + (size_t)row * 16;
    if (tie) {
        int pos = wbase + __popc(mask & ((1u << lane) - 1u));
        g_rrows[rbase + pos] = row;
    } else {
        const float4* eb = (const float4*)emb + (size_t)idx1 * 16;
        float4* op = (float4*)out + (size_t)row * 16;
        #pragma unroll
        for (int j = 0; j < 16; ++j) {
            float4 q = eb[j];
            float4 zv = zp[j];
            op[j] = q;
            float dx = q.x - zv.x, dy = q.y - zv.y;
            float dz = q.z - zv.z, dw = q.w - zv.w;
            lacc += (double)dx * dx + (double)dy * dy
                  + (double)dz * dz + (double)dw * dw;
        }
    }
    #pragma unroll
    for (int off = 16; off; off >>= 1)
        lacc += __shfl_down_sync(0xffffffffu, lacc, off);
    if (lane == 0) s_red[warp] = lacc;
    __syncthreads();
    if (tid == 0) {
        g_rcnt[blockIdx.x] = s_wc[0] + s_wc[1] + s_wc[2] + s_wc[3];
        g_part[blockIdx.x] = s_red[0] + s_red[1] + s_red[2] + s_red[3];
    }
}

// Exact fp32 rescan (R1 arithmetic) for near-tie rows + fused final reduce.
__global__ __launch_bounds__(256)
void vq_rescore_fin_kernel(const float* __restrict__ z,
                           const float* __restrict__ emb,
                           float* __restrict__ out, int out_size) {
    __shared__ float s_emb[128 * 69];
    __shared__ float s_zrow[RW * 64];
    __shared__ int   s_rows[RW];
    __shared__ double s_red[8];
    __shared__ int   s_last;

    const int b = blockIdx.x;
    const int n = g_rcnt[b];
    const int tid = threadIdx.x;
    const int w = tid >> 5, l = tid & 31;

    double wacc = 0.0;
    for (int base = 0; base < n; base += RW) {
        __syncthreads();
        if (tid < RW)
            s_rows[tid] = (base + tid < n) ? g_rrows[b * BLOCK + base + tid] : -1;
        __syncthreads();
        if (tid < RW * 16) {
            int rw = tid >> 4, j = tid & 15;
            int r = s_rows[rw];
            if (r >= 0)
                *(float4*)(s_zrow + rw * 64 + j * 4) = ((const float4*)z)[(size_t)r * 16 + j];
        }
        __syncthreads();

        int myrow = s_rows[w];
        float zz = 0.f;
        if (myrow >= 0)
            for (int i = 0; i < 64; ++i) { float v = s_zrow[w * 64 + i]; zz += v * v; }

        float dmin = 3.4e38f;
        int   bestk = 0;

        for (int tt = 0; tt < K / 128; ++tt) {
            __syncthreads();
            for (int f = tid; f < 128 * 16; f += 256) {
                int e = f >> 4, j = f & 15;
                float4 v = ((const float4*)emb)[(size_t)(tt * 128 + e) * 16 + j];
                float* dst = s_emb + e * 69 + j * 4;
                dst[0] = v.x; dst[1] = v.y; dst[2] = v.z; dst[3] = v.w;
            }
            __syncthreads();
            if (myrow >= 0) {
                #pragma unroll
                for (int q = 0; q < 4; ++q) {
                    int el = q * 32 + l;
                    const float* e = s_emb + el * 69;
                    float ze = 0.f;
                    for (int i = 0; i < 64; ++i) ze += s_zrow[w * 64 + i] * e[i];
                    int ge = tt * 128 + el;
                    float d = (zz - 2.0f * ze) + g_ee[ge];
                    if (d < dmin) { dmin = d; bestk = ge; }
                }
            }
        }

        #pragma unroll
        for (int off = 16; off; off >>= 1) {
            float od = __shfl_down_sync(0xffffffffu, dmin, off);
            int   oi = __shfl_down_sync(0xffffffffu, bestk, off);
            if (od < dmin || (od == dmin && oi < bestk)) { dmin = od; bestk = oi; }
        }

        if (myrow >= 0 && l == 0) {
            const float4* eb = (const float4*)emb + (size_t)bestk * 16;
            float4* op = (float4*)out + (size_t)myrow * 16;
            for (int j = 0; j < 16; ++j) {
                float4 q = eb[j];
                float zx = s_zrow[w * 64 + j * 4 + 0];
                float zy = s_zrow[w * 64 + j * 4 + 1];
                float zzv = s_zrow[w * 64 + j * 4 + 2];
                float zw = s_zrow[w * 64 + j * 4 + 3];
                op[j] = q;
                float dx = q.x - zx, dy = q.y - zy, dz = q.z - zzv, dw = q.w - zw;
                wacc += (double)dx * dx + (double)dy * dy
                      + (double)dz * dz + (double)dw * dw;
            }
        }
    }
    __syncthreads();
    if (l == 0) s_red[w] = wacc;
    __syncthreads();
    if (tid == 0) {
        double s2 = 0.0;
        #pragma unroll
        for (int i = 0; i < 8; ++i) s2 += s_red[i];
        g_part2[b] = s2;
        __threadfence();
        s_last = (atomicAdd(&g_done, 1) == gridDim.x - 1);
    }
    __syncthreads();
    if (s_last) {
        // Last block: deterministic final reduction over fixed index order.
        double v = 0.0;
        for (int i = tid; i < NCTAS; i += 256)
            v += g_part[i] + g_part2[i];
        #pragma unroll
        for (int off = 16; off; off >>= 1)
            v += __shfl_down_sync(0xffffffffu, v, off);
        if (l == 0) s_red[w] = v;
        __syncthreads();
        if (tid == 0) {
            double s = 0.0;
            #pragma unroll
            for (int i = 0; i < 8; ++i) s += s_red[i];
            if (out_size > NROWS * D)
                out[NROWS * D] = (float)(1.25 * s / (double)((long long)NROWS * D));
            g_done = 0;   // reset for next graph replay
        }
    }
}

extern "C" void kernel_launch(void* const* d_in, const int* in_sizes, int n_in,
                              void* d_out, int out_size) {
    const float* z   = (const float*)d_in[0];
    const float* emb = (const float*)d_in[1];
    if (n_in >= 2 && in_sizes[0] == K * D && in_sizes[1] == NROWS * D) {
        z   = (const float*)d_in[1];
        emb = (const float*)d_in[0];
    }
    float* out = (float*)d_out;

    vq_pre_kernel<<<8, 128>>>(emb);
    vq_main_kernel<<<NCTAS, BLOCK>>>(z, emb, out);
    vq_rescore_fin_kernel<<<NCTAS, 256>>>(z, emb, out, out_size);
}